// round 5
// baseline (speedup 1.0000x reference)
#include <cuda_runtime.h>
#include <math.h>
#include <stdint.h>

#define B_ 8
#define T_ 2048
#define C_ 1024
#define H_ 128

// Scratch for k (=q) and v projections: [B, T, H] fp32 each (8 MB each).
__device__ float g_k[B_ * T_ * H_];
__device__ float g_v[B_ * T_ * H_];

// ---- cp.async helpers ----
__device__ __forceinline__ unsigned smem_u32(const void* p) {
  return (unsigned)__cvta_generic_to_shared(p);
}
__device__ __forceinline__ void cp_async16(unsigned saddr, const void* gptr) {
  asm volatile("cp.async.cg.shared.global [%0], [%1], 16;\n" ::"r"(saddr),
               "l"(gptr));
}
__device__ __forceinline__ void cp_async_commit() {
  asm volatile("cp.async.commit_group;\n");
}
template <int N>
__device__ __forceinline__ void cp_async_wait() {
  asm volatile("cp.async.wait_group %0;\n" ::"n"(N));
}

// ---- TF32 helpers ----
__device__ __forceinline__ float to_tf32(float x) {
  uint32_t u;
  asm("cvt.rna.tf32.f32 %0, %1;" : "=r"(u) : "f"(x));
  return __uint_as_float(u);
}
// D += A(16x8,row) * B(8x8,col) ; tf32 inputs (b32 regs), f32 accum.
__device__ __forceinline__ void mma_tf32(float c[4], uint32_t a0, uint32_t a1,
                                         uint32_t a2, uint32_t a3, uint32_t b0,
                                         uint32_t b1) {
  asm volatile(
      "mma.sync.aligned.m16n8k8.row.col.f32.tf32.tf32.f32 "
      "{%0,%1,%2,%3}, {%4,%5,%6,%7}, {%8,%9}, {%0,%1,%2,%3};"
      : "+f"(c[0]), "+f"(c[1]), "+f"(c[2]), "+f"(c[3])
      : "r"(a0), "r"(a1), "r"(a2), "r"(a3), "r"(b0), "r"(b1));
}

// ---------------------------------------------------------------------------
// Kernel 1: fused projections via TF32 mma.sync.
//   k[bt,h] = sum_c x[bt,c]*Wk[h,c]   (and v with Wv; blockIdx.y selects)
// Block tile 128(M) x 128(N=H), K-chunk 32, 256 threads = 8 warps (2x4).
// Warp tile 64(M) x 32(N): 4 m-tiles x 4 n-tiles of m16n8k8 per k-step.
// Smem tiles [row][36] (stride-36 pad): fragment LDS bank = (4*(lane/4)+
// lane%4 + const)%32 -> conflict-free. Inputs rounded to TF32 (cvt.rna) at
// staging. Register prefetch hides next chunk's LDG latency under the mma.
// ---------------------------------------------------------------------------
__global__ __launch_bounds__(256) void proj_kernel(
    const float* __restrict__ x, const float* __restrict__ Wk,
    const float* __restrict__ Wv) {
  __shared__ float Xs[128][36];   // [m][k]  (36 = 32 + 4 pad)
  __shared__ float Ws[128][36];   // [n=h][k]
  const float* __restrict__ W = (blockIdx.y == 0) ? Wk : Wv;
  float* __restrict__ outp = (blockIdx.y == 0) ? g_k : g_v;
  const int m_base = blockIdx.x * 128;
  const int tid = threadIdx.x;
  const int warp = tid >> 5, lane = tid & 31;
  const int wm = warp >> 2;            // 0..1  -> m offset 0/64
  const int wn = warp & 3;             // 0..3  -> n offset 0/32/64/96
  const int m_w = wm * 64, n_w = wn * 32;
  const int g = lane >> 2;             // group id 0..7
  const int t = lane & 3;              // thread-in-group 0..3

  // Staging slots: 4 float4 each for X and W; kc fixed, rows tid>>3 + 32*i.
  const int s_kc = (tid & 7) << 2;     // 0,4,...,28
  const int s_r0 = tid >> 3;           // 0..31

  float acc[4][4][4];
#pragma unroll
  for (int i = 0; i < 4; i++)
#pragma unroll
    for (int j = 0; j < 4; j++)
#pragma unroll
      for (int r = 0; r < 4; r++) acc[i][j][r] = 0.f;

  // Prefetch chunk 0.
  float4 px[4], pw[4];
#pragma unroll
  for (int i = 0; i < 4; i++) {
    int row = s_r0 + 32 * i;
    px[i] = *reinterpret_cast<const float4*>(
        &x[(size_t)(m_base + row) * C_ + s_kc]);
    pw[i] = *reinterpret_cast<const float4*>(&W[(size_t)row * C_ + s_kc]);
  }

  for (int k0 = 0; k0 < C_; k0 += 32) {
    // Scatter (TF32-rounded) into smem tiles.
#pragma unroll
    for (int i = 0; i < 4; i++) {
      int row = s_r0 + 32 * i;
      float4 xv = px[i], wv = pw[i];
      *reinterpret_cast<float4*>(&Xs[row][s_kc]) =
          make_float4(to_tf32(xv.x), to_tf32(xv.y), to_tf32(xv.z),
                      to_tf32(xv.w));
      *reinterpret_cast<float4*>(&Ws[row][s_kc]) =
          make_float4(to_tf32(wv.x), to_tf32(wv.y), to_tf32(wv.z),
                      to_tf32(wv.w));
    }
    __syncthreads();

    // Prefetch next chunk (drains during mma block).
    if (k0 + 32 < C_) {
      const int kn = k0 + 32;
#pragma unroll
      for (int i = 0; i < 4; i++) {
        int row = s_r0 + 32 * i;
        px[i] = *reinterpret_cast<const float4*>(
            &x[(size_t)(m_base + row) * C_ + kn + s_kc]);
        pw[i] = *reinterpret_cast<const float4*>(&W[(size_t)row * C_ + kn + s_kc]);
      }
    }

#pragma unroll
    for (int ks = 0; ks < 4; ks++) {
      const int kk = ks * 8 + t;
      uint32_t A[4][4];
#pragma unroll
      for (int i = 0; i < 4; i++) {
        const int ar = m_w + i * 16 + g;
        A[i][0] = __float_as_uint(Xs[ar][kk]);
        A[i][1] = __float_as_uint(Xs[ar + 8][kk]);
        A[i][2] = __float_as_uint(Xs[ar][kk + 4]);
        A[i][3] = __float_as_uint(Xs[ar + 8][kk + 4]);
      }
      uint32_t Bf[4][2];
#pragma unroll
      for (int j = 0; j < 4; j++) {
        const int br = n_w + j * 8 + g;
        Bf[j][0] = __float_as_uint(Ws[br][kk]);
        Bf[j][1] = __float_as_uint(Ws[br][kk + 4]);
      }
#pragma unroll
      for (int i = 0; i < 4; i++)
#pragma unroll
        for (int j = 0; j < 4; j++)
          mma_tf32(acc[i][j], A[i][0], A[i][1], A[i][2], A[i][3], Bf[j][0],
                   Bf[j][1]);
    }
    __syncthreads();
  }

  // Epilogue: c0/c1 -> (row, 2t/2t+1), c2/c3 -> (row+8, ...).
#pragma unroll
  for (int i = 0; i < 4; i++) {
#pragma unroll
    for (int j = 0; j < 4; j++) {
      const int r0 = m_base + m_w + i * 16 + g;
      const int c0 = n_w + j * 8 + 2 * t;
      *reinterpret_cast<float2*>(&outp[(size_t)r0 * H_ + c0]) =
          make_float2(acc[i][j][0], acc[i][j][1]);
      *reinterpret_cast<float2*>(&outp[(size_t)(r0 + 8) * H_ + c0]) =
          make_float2(acc[i][j][2], acc[i][j][3]);
    }
  }
}

// ---------------------------------------------------------------------------
// Kernel 2: causal flash attention with q == k.  (unchanged, audited fp32)
// Br=Bc=64, D=128, 256 threads (16x16). Online softmax. scale = C^-0.5 = 1/32.
// K and V staged as SEPARATE cp.async groups: score GEMM waits only on K
// (wait_group 1); V's latency hidden under score+softmax (wait_group 0).
// ---------------------------------------------------------------------------
#define FA_SMEM_BYTES ((3 * 64 * 128 + 64 * 68) * 4)

__global__ __launch_bounds__(256, 2) void flash_kernel(float* __restrict__ out) {
  extern __shared__ float sm[];
  float* Qs = sm;                    // 64*128 swizzled
  float* Ks = Qs + 64 * 128;         // 64*128 swizzled
  float* Vs = Ks + 64 * 128;         // 64*128 row-major
  float* Ps = Vs + 64 * 128;         // 64 x 68

  const int bid = blockIdx.x;
  const int item = (bid < 148) ? bid : (403 - bid);
  const int qt = 31 - (item >> 3);
  const int batch = item & 7;
  const int tid = threadIdx.x;
  const int ty = tid >> 4, tx = tid & 15;
  const float* __restrict__ kb = g_k + (size_t)batch * T_ * H_;
  const float* __restrict__ vb = g_v + (size_t)batch * T_ * H_;

  {
    const int t0 = qt * 64;
#pragma unroll
    for (int i = 0; i < 8; i++) {
      int slot = tid + i * 256;
      int row = slot >> 5, f = slot & 31;
      int fs = f ^ ((row >> 2) & 7);
      cp_async16(smem_u32(&Qs[row * 128 + fs * 4]),
                 &kb[(size_t)(t0 + row) * H_ + f * 4]);
    }
    cp_async_commit();
  }

  float m[4], l[4], o[4][8];
#pragma unroll
  for (int i = 0; i < 4; i++) {
    m[i] = -INFINITY;
    l[i] = 0.f;
#pragma unroll
    for (int j = 0; j < 8; j++) o[i][j] = 0.f;
  }
  const float4* __restrict__ Vs4 = reinterpret_cast<const float4*>(Vs);

  for (int kt = 0; kt <= qt; kt++) {
    const int t0 = kt * 64;
#pragma unroll
    for (int i = 0; i < 8; i++) {
      int slot = tid + i * 256;
      int row = slot >> 5, f = slot & 31;
      int fs = f ^ ((row >> 2) & 7);
      cp_async16(smem_u32(&Ks[row * 128 + fs * 4]),
                 &kb[(size_t)(t0 + row) * H_ + f * 4]);
    }
    cp_async_commit();
#pragma unroll
    for (int i = 0; i < 8; i++) {
      int slot = tid + i * 256;
      int row = slot >> 5, f = slot & 31;
      cp_async16(smem_u32(&Vs[row * 128 + f * 4]),
                 &vb[(size_t)(t0 + row) * H_ + f * 4]);
    }
    cp_async_commit();

    cp_async_wait<1>();
    __syncthreads();

    float acc[4][4];
#pragma unroll
    for (int i = 0; i < 4; i++)
#pragma unroll
      for (int j = 0; j < 4; j++) acc[i][j] = 0.f;

    const int swa = ty & 7, swb = tx & 7;
    const int qb = (ty * 4) * 128;
    const int kbb = (tx * 4) * 128;
#pragma unroll 8
    for (int d4 = 0; d4 < 32; d4++) {
      const int fa = (d4 ^ swa) << 2;
      const int fb = (d4 ^ swb) << 2;
      float4 a0 = *reinterpret_cast<const float4*>(&Qs[qb + fa]);
      float4 a1 = *reinterpret_cast<const float4*>(&Qs[qb + 128 + fa]);
      float4 a2 = *reinterpret_cast<const float4*>(&Qs[qb + 256 + fa]);
      float4 a3 = *reinterpret_cast<const float4*>(&Qs[qb + 384 + fa]);
      float4 b0 = *reinterpret_cast<const float4*>(&Ks[kbb + fb]);
      float4 b1 = *reinterpret_cast<const float4*>(&Ks[kbb + 128 + fb]);
      float4 b2 = *reinterpret_cast<const float4*>(&Ks[kbb + 256 + fb]);
      float4 b3 = *reinterpret_cast<const float4*>(&Ks[kbb + 384 + fb]);
      float4 A[4] = {a0, a1, a2, a3};
      float4 Bv[4] = {b0, b1, b2, b3};
#pragma unroll
      for (int i = 0; i < 4; i++)
#pragma unroll
        for (int j = 0; j < 4; j++) {
          acc[i][j] += A[i].x * Bv[j].x + A[i].y * Bv[j].y +
                       A[i].z * Bv[j].z + A[i].w * Bv[j].w;
        }
    }

    const bool diag = (kt == qt);
#pragma unroll
    for (int i = 0; i < 4; i++)
#pragma unroll
      for (int j = 0; j < 4; j++) {
        float s = acc[i][j] * 0.03125f;
        if (diag && (tx * 4 + j) > (ty * 4 + i)) s = -INFINITY;
        acc[i][j] = s;
      }

#pragma unroll
    for (int i = 0; i < 4; i++) {
      float mt = fmaxf(fmaxf(acc[i][0], acc[i][1]), fmaxf(acc[i][2], acc[i][3]));
#pragma unroll
      for (int off = 8; off > 0; off >>= 1)
        mt = fmaxf(mt, __shfl_xor_sync(0xffffffffu, mt, off, 16));
      float mnew = fmaxf(m[i], mt);
      float alpha = __expf(m[i] - mnew);
      m[i] = mnew;
      float ls = 0.f;
#pragma unroll
      for (int j = 0; j < 4; j++) {
        float p = __expf(acc[i][j] - mnew);
        acc[i][j] = p;
        ls += p;
      }
#pragma unroll
      for (int off = 8; off > 0; off >>= 1)
        ls += __shfl_xor_sync(0xffffffffu, ls, off, 16);
      l[i] = l[i] * alpha + ls;
#pragma unroll
      for (int j = 0; j < 8; j++) o[i][j] *= alpha;
#pragma unroll
      for (int j = 0; j < 4; j++)
        Ps[(ty * 4 + i) * 68 + tx * 4 + j] = acc[i][j];
    }
    cp_async_wait<0>();
    __syncthreads();

#pragma unroll 4
    for (int c = 0; c < 64; c++) {
      float4 v0 = Vs4[c * 32 + tx];
      float4 v1 = Vs4[c * 32 + 16 + tx];
#pragma unroll
      for (int i = 0; i < 4; i++) {
        float p = Ps[(ty * 4 + i) * 68 + c];
        o[i][0] += p * v0.x; o[i][1] += p * v0.y;
        o[i][2] += p * v0.z; o[i][3] += p * v0.w;
        o[i][4] += p * v1.x; o[i][5] += p * v1.y;
        o[i][6] += p * v1.z; o[i][7] += p * v1.w;
      }
    }
    __syncthreads();
  }

#pragma unroll
  for (int i = 0; i < 4; i++) {
    float inv = 1.f / l[i];
    int row = qt * 64 + ty * 4 + i;
    float* orow = &out[((size_t)batch * T_ + row) * H_];
    float4 w0 = make_float4(o[i][0] * inv, o[i][1] * inv, o[i][2] * inv, o[i][3] * inv);
    float4 w1 = make_float4(o[i][4] * inv, o[i][5] * inv, o[i][6] * inv, o[i][7] * inv);
    *reinterpret_cast<float4*>(&orow[tx * 4]) = w0;
    *reinterpret_cast<float4*>(&orow[64 + tx * 4]) = w1;
  }
}

// ---------------------------------------------------------------------------
extern "C" void kernel_launch(void* const* d_in, const int* in_sizes, int n_in,
                              void* d_out, int out_size) {
  (void)in_sizes; (void)n_in; (void)out_size;
  const float* x  = (const float*)d_in[0];
  const float* Wk = (const float*)d_in[1];
  // d_in[2] is Wq — unused (reference uses Wk for q too).
  const float* Wv = (const float*)d_in[3];
  float* out = (float*)d_out;

  proj_kernel<<<dim3(128, 2), 256>>>(x, Wk, Wv);

  cudaFuncSetAttribute(flash_kernel,
                       cudaFuncAttributeMaxDynamicSharedMemorySize,
                       FA_SMEM_BYTES);
  flash_kernel<<<256, 256, FA_SMEM_BYTES>>>(out);
}

// round 14
// speedup vs baseline: 2.2069x; 2.2069x over previous
#include <cuda_runtime.h>
#include <math.h>
#include <stdint.h>

#define B_ 8
#define T_ 2048
#define C_ 1024
#define H_ 128

// Scratch for k (=q, pre-scaled by C^-0.25 per factor) and v: [B,T,H] fp32.
__device__ float g_k[B_ * T_ * H_];
__device__ float g_v[B_ * T_ * H_];

// ---- cp.async helpers ----
__device__ __forceinline__ unsigned smem_u32(const void* p) {
  return (unsigned)__cvta_generic_to_shared(p);
}
__device__ __forceinline__ void cp_async16(unsigned saddr, const void* gptr) {
  asm volatile("cp.async.cg.shared.global [%0], [%1], 16;\n" ::"r"(saddr),
               "l"(gptr));
}
__device__ __forceinline__ void cp_async_commit() {
  asm volatile("cp.async.commit_group;\n");
}
template <int N>
__device__ __forceinline__ void cp_async_wait() {
  asm volatile("cp.async.wait_group %0;\n" ::"n"(N));
}

// ---- TF32 helpers (layouts validated on HW by round-5 proj kernel) ----
__device__ __forceinline__ float to_tf32(float x) {
  uint32_t u;
  asm("cvt.rna.tf32.f32 %0, %1;" : "=r"(u) : "f"(x));
  return __uint_as_float(u);
}
__device__ __forceinline__ void mma_tf32(float c[4], uint32_t a0, uint32_t a1,
                                         uint32_t a2, uint32_t a3, uint32_t b0,
                                         uint32_t b1) {
  asm volatile(
      "mma.sync.aligned.m16n8k8.row.col.f32.tf32.tf32.f32 "
      "{%0,%1,%2,%3}, {%4,%5,%6,%7}, {%8,%9}, {%0,%1,%2,%3};"
      : "+f"(c[0]), "+f"(c[1]), "+f"(c[2]), "+f"(c[3])
      : "r"(a0), "r"(a1), "r"(a2), "r"(a3), "r"(b0), "r"(b1));
}

// ---------------------------------------------------------------------------
// Kernel 1: fused projections via TF32 mma.sync (validated round 5).
// g_k output pre-scaled by C^-0.25 = 2^-2.5 (q==k -> score picks up C^-0.5);
// outputs tf32-rounded so flash can feed mma without re-rounding.
// ---------------------------------------------------------------------------
__global__ __launch_bounds__(256) void proj_kernel(
    const float* __restrict__ x, const float* __restrict__ Wk,
    const float* __restrict__ Wv) {
  __shared__ float Xs[128][36];
  __shared__ float Ws[128][36];
  const float* __restrict__ W = (blockIdx.y == 0) ? Wk : Wv;
  float* __restrict__ outp = (blockIdx.y == 0) ? g_k : g_v;
  const float oscale = (blockIdx.y == 0) ? 0.17677669529663689f : 1.0f;
  const int m_base = blockIdx.x * 128;
  const int tid = threadIdx.x;
  const int warp = tid >> 5, lane = tid & 31;
  const int wm = warp >> 2, wn = warp & 3;
  const int m_w = wm * 64, n_w = wn * 32;
  const int g = lane >> 2, t = lane & 3;
  const int s_kc = (tid & 7) << 2;
  const int s_r0 = tid >> 3;

  float acc[4][4][4];
#pragma unroll
  for (int i = 0; i < 4; i++)
#pragma unroll
    for (int j = 0; j < 4; j++)
#pragma unroll
      for (int r = 0; r < 4; r++) acc[i][j][r] = 0.f;

  float4 px[4], pw[4];
#pragma unroll
  for (int i = 0; i < 4; i++) {
    int row = s_r0 + 32 * i;
    px[i] = *reinterpret_cast<const float4*>(
        &x[(size_t)(m_base + row) * C_ + s_kc]);
    pw[i] = *reinterpret_cast<const float4*>(&W[(size_t)row * C_ + s_kc]);
  }

  for (int k0 = 0; k0 < C_; k0 += 32) {
#pragma unroll
    for (int i = 0; i < 4; i++) {
      int row = s_r0 + 32 * i;
      float4 xv = px[i], wv = pw[i];
      *reinterpret_cast<float4*>(&Xs[row][s_kc]) =
          make_float4(to_tf32(xv.x), to_tf32(xv.y), to_tf32(xv.z),
                      to_tf32(xv.w));
      *reinterpret_cast<float4*>(&Ws[row][s_kc]) =
          make_float4(to_tf32(wv.x), to_tf32(wv.y), to_tf32(wv.z),
                      to_tf32(wv.w));
    }
    __syncthreads();

    if (k0 + 32 < C_) {
      const int kn = k0 + 32;
#pragma unroll
      for (int i = 0; i < 4; i++) {
        int row = s_r0 + 32 * i;
        px[i] = *reinterpret_cast<const float4*>(
            &x[(size_t)(m_base + row) * C_ + kn + s_kc]);
        pw[i] = *reinterpret_cast<const float4*>(&W[(size_t)row * C_ + kn + s_kc]);
      }
    }

#pragma unroll
    for (int ks = 0; ks < 4; ks++) {
      const int kk = ks * 8 + t;
      uint32_t A[4][4];
#pragma unroll
      for (int i = 0; i < 4; i++) {
        const int ar = m_w + i * 16 + g;
        A[i][0] = __float_as_uint(Xs[ar][kk]);
        A[i][1] = __float_as_uint(Xs[ar + 8][kk]);
        A[i][2] = __float_as_uint(Xs[ar][kk + 4]);
        A[i][3] = __float_as_uint(Xs[ar + 8][kk + 4]);
      }
      uint32_t Bf[4][2];
#pragma unroll
      for (int j = 0; j < 4; j++) {
        const int br = n_w + j * 8 + g;
        Bf[j][0] = __float_as_uint(Ws[br][kk]);
        Bf[j][1] = __float_as_uint(Ws[br][kk + 4]);
      }
#pragma unroll
      for (int i = 0; i < 4; i++)
#pragma unroll
        for (int j = 0; j < 4; j++)
          mma_tf32(acc[i][j], A[i][0], A[i][1], A[i][2], A[i][3], Bf[j][0],
                   Bf[j][1]);
    }
    __syncthreads();
  }

#pragma unroll
  for (int i = 0; i < 4; i++) {
#pragma unroll
    for (int j = 0; j < 4; j++) {
      const int r0 = m_base + m_w + i * 16 + g;
      const int c0 = n_w + j * 8 + 2 * t;
      *reinterpret_cast<float2*>(&outp[(size_t)r0 * H_ + c0]) =
          make_float2(to_tf32(acc[i][j][0] * oscale),
                      to_tf32(acc[i][j][1] * oscale));
      *reinterpret_cast<float2*>(&outp[(size_t)(r0 + 8) * H_ + c0]) =
          make_float2(to_tf32(acc[i][j][2] * oscale),
                      to_tf32(acc[i][j][3] * oscale));
    }
  }
}

// ---------------------------------------------------------------------------
// Kernel 2: causal flash attention (q==k), TF32 mma.sync everywhere.
// Br=Bc=64, D=128, 256 thr = 8 warps as 4(m)x2(n). Warp score tile m16xn32.
// Smem: Qs[64][132], Ks[64][132] (P aliases Ks after score), Vs[64][136]
//   -> 100KB dynamic -> 2 CTAs/SM. Pads make every frag LDS conflict-free.
// Cross-warp softmax via red_max/red_sum[64][2]. 4 barriers/iter.
// Scale already folded into g_k. P tf32-rounded before PV.
// ---------------------------------------------------------------------------
#define QK_STRIDE 132
#define V_STRIDE 136
#define FA_SMEM_BYTES ((2 * 64 * QK_STRIDE + 64 * V_STRIDE) * 4)

__global__ __launch_bounds__(256, 2) void flash_kernel(float* __restrict__ out) {
  extern __shared__ float smf[];
  float* Qs = smf;                         // [64][132]
  float* Ks = Qs + 64 * QK_STRIDE;         // [64][132]; P lives here after score
  float* Vs = Ks + 64 * QK_STRIDE;         // [64][136]
  __shared__ float red_max[64][2];
  __shared__ float red_sum[64][2];

  const int bid = blockIdx.x;
  const int item = (bid < 148) ? bid : (403 - bid);
  const int qt = 31 - (item >> 3);
  const int batch = item & 7;
  const int tid = threadIdx.x;
  const int warp = tid >> 5, lane = tid & 31;
  const int wm = warp >> 1;                // 0..3 -> m offset 16*wm
  const int wn = warp & 1;                 // 0..1
  const int g = lane >> 2, t = lane & 3;
  const int r0 = wm * 16 + g, r1 = r0 + 8; // CTA-local q rows owned

  const float* __restrict__ kb = g_k + (size_t)batch * T_ * H_;
  const float* __restrict__ vb = g_v + (size_t)batch * T_ * H_;

  // Q tile via cp.async (group 0).
  {
    const int tq = qt * 64;
#pragma unroll
    for (int i = 0; i < 8; i++) {
      int slot = tid + i * 256;
      int row = slot >> 5, f = slot & 31;
      cp_async16(smem_u32(&Qs[row * QK_STRIDE + f * 4]),
                 &kb[(size_t)(tq + row) * H_ + f * 4]);
    }
    cp_async_commit();
  }

  float m0 = -INFINITY, m1 = -INFINITY, l0 = 0.f, l1 = 0.f;
  float o[8][4];
#pragma unroll
  for (int jj = 0; jj < 8; jj++)
#pragma unroll
    for (int c = 0; c < 4; c++) o[jj][c] = 0.f;

  for (int kt = 0; kt <= qt; kt++) {
    const int tk = kt * 64;
    // K tile -> group; V tile -> separate group (in flight through score).
#pragma unroll
    for (int i = 0; i < 8; i++) {
      int slot = tid + i * 256;
      int row = slot >> 5, f = slot & 31;
      cp_async16(smem_u32(&Ks[row * QK_STRIDE + f * 4]),
                 &kb[(size_t)(tk + row) * H_ + f * 4]);
    }
    cp_async_commit();
#pragma unroll
    for (int i = 0; i < 8; i++) {
      int slot = tid + i * 256;
      int row = slot >> 5, f = slot & 31;
      cp_async16(smem_u32(&Vs[row * V_STRIDE + f * 4]),
                 &vb[(size_t)(tk + row) * H_ + f * 4]);
    }
    cp_async_commit();

    cp_async_wait<1>();        // Q(iter0)+K retired; V in flight
    __syncthreads();           // (1) K visible to all

    // ---- score S = Q K^T (scale pre-folded): warp tile m16 x n32 ----
    float sc[4][4];
#pragma unroll
    for (int j = 0; j < 4; j++)
#pragma unroll
      for (int c = 0; c < 4; c++) sc[j][c] = 0.f;

#pragma unroll
    for (int ks = 0; ks < 16; ks++) {
      const int kk = ks * 8 + t;
      uint32_t a0 = __float_as_uint(Qs[r0 * QK_STRIDE + kk]);
      uint32_t a1 = __float_as_uint(Qs[r1 * QK_STRIDE + kk]);
      uint32_t a2 = __float_as_uint(Qs[r0 * QK_STRIDE + kk + 4]);
      uint32_t a3 = __float_as_uint(Qs[r1 * QK_STRIDE + kk + 4]);
#pragma unroll
      for (int j = 0; j < 4; j++) {
        const int br = wn * 32 + j * 8 + g;
        uint32_t b0 = __float_as_uint(Ks[br * QK_STRIDE + kk]);
        uint32_t b1 = __float_as_uint(Ks[br * QK_STRIDE + kk + 4]);
        mma_tf32(sc[j], a0, a1, a2, a3, b0, b1);
      }
    }

    // ---- causal mask (diagonal tile only) ----
    if (kt == qt) {
#pragma unroll
      for (int j = 0; j < 4; j++) {
        const int cb = wn * 32 + j * 8 + 2 * t;
        if (cb > r0) sc[j][0] = -INFINITY;
        if (cb + 1 > r0) sc[j][1] = -INFINITY;
        if (cb > r1) sc[j][2] = -INFINITY;
        if (cb + 1 > r1) sc[j][3] = -INFINITY;
      }
    }

    // ---- online softmax: cross-warp (wn) reduction via smem ----
    float mx0 = -INFINITY, mx1 = -INFINITY;
#pragma unroll
    for (int j = 0; j < 4; j++) {
      mx0 = fmaxf(mx0, fmaxf(sc[j][0], sc[j][1]));
      mx1 = fmaxf(mx1, fmaxf(sc[j][2], sc[j][3]));
    }
    mx0 = fmaxf(mx0, __shfl_xor_sync(0xffffffffu, mx0, 1));
    mx0 = fmaxf(mx0, __shfl_xor_sync(0xffffffffu, mx0, 2));
    mx1 = fmaxf(mx1, __shfl_xor_sync(0xffffffffu, mx1, 1));
    mx1 = fmaxf(mx1, __shfl_xor_sync(0xffffffffu, mx1, 2));
    if (t == 0) {
      red_max[r0][wn] = mx0;
      red_max[r1][wn] = mx1;
    }
    __syncthreads();           // (2) partial maxima visible

    const float M0 = fmaxf(m0, fmaxf(red_max[r0][0], red_max[r0][1]));
    const float M1 = fmaxf(m1, fmaxf(red_max[r1][0], red_max[r1][1]));
    const float al0 = __expf(m0 - M0);
    const float al1 = __expf(m1 - M1);
    m0 = M0; m1 = M1;

    float s0 = 0.f, s1 = 0.f;
#pragma unroll
    for (int j = 0; j < 4; j++) {
      sc[j][0] = to_tf32(__expf(sc[j][0] - M0));
      sc[j][1] = to_tf32(__expf(sc[j][1] - M0));
      sc[j][2] = to_tf32(__expf(sc[j][2] - M1));
      sc[j][3] = to_tf32(__expf(sc[j][3] - M1));
      s0 += sc[j][0] + sc[j][1];
      s1 += sc[j][2] + sc[j][3];
    }
    s0 += __shfl_xor_sync(0xffffffffu, s0, 1);
    s0 += __shfl_xor_sync(0xffffffffu, s0, 2);
    s1 += __shfl_xor_sync(0xffffffffu, s1, 1);
    s1 += __shfl_xor_sync(0xffffffffu, s1, 2);
    if (t == 0) {
      red_sum[r0][wn] = s0;
      red_sum[r1][wn] = s1;
    }

    // P -> Ks buffer (K is dead after score; all warps past barrier (2)).
    float* Ps = Ks;
#pragma unroll
    for (int j = 0; j < 4; j++) {
      const int col = wn * 32 + j * 8 + 2 * t;
      *reinterpret_cast<float2*>(&Ps[r0 * QK_STRIDE + col]) =
          make_float2(sc[j][0], sc[j][1]);
      *reinterpret_cast<float2*>(&Ps[r1 * QK_STRIDE + col]) =
          make_float2(sc[j][2], sc[j][3]);
    }
    cp_async_wait<0>();        // V retired (latency hidden by score+softmax)
    __syncthreads();           // (3) P, sums, V visible

    l0 = l0 * al0 + red_sum[r0][0] + red_sum[r0][1];
    l1 = l1 * al1 + red_sum[r1][0] + red_sum[r1][1];
#pragma unroll
    for (int jj = 0; jj < 8; jj++) {
      o[jj][0] *= al0; o[jj][1] *= al0;
      o[jj][2] *= al1; o[jj][3] *= al1;
    }

    // ---- O += P @ V : warp tile m16 x n64 over headdim half wn ----
#pragma unroll
    for (int ks = 0; ks < 8; ks++) {
      const int kk = ks * 8 + t;
      uint32_t a0 = __float_as_uint(Ps[r0 * QK_STRIDE + kk]);
      uint32_t a1 = __float_as_uint(Ps[r1 * QK_STRIDE + kk]);
      uint32_t a2 = __float_as_uint(Ps[r0 * QK_STRIDE + kk + 4]);
      uint32_t a3 = __float_as_uint(Ps[r1 * QK_STRIDE + kk + 4]);
#pragma unroll
      for (int jj = 0; jj < 8; jj++) {
        const int vc = wn * 64 + jj * 8 + g;
        uint32_t b0 = __float_as_uint(Vs[kk * V_STRIDE + vc]);
        uint32_t b1 = __float_as_uint(Vs[(kk + 4) * V_STRIDE + vc]);
        mma_tf32(o[jj], a0, a1, a2, a3, b0, b1);
      }
    }
    __syncthreads();           // (4) PV done; Ks safe for next K cp.async
  }

  // ---- epilogue ----
  const float inv0 = 1.f / l0, inv1 = 1.f / l1;
  const size_t rowA = (size_t)batch * T_ + qt * 64 + r0;
  const size_t rowB = (size_t)batch * T_ + qt * 64 + r1;
#pragma unroll
  for (int jj = 0; jj < 8; jj++) {
    const int col = wn * 64 + jj * 8 + 2 * t;
    *reinterpret_cast<float2*>(&out[rowA * H_ + col]) =
        make_float2(o[jj][0] * inv0, o[jj][1] * inv0);
    *reinterpret_cast<float2*>(&out[rowB * H_ + col]) =
        make_float2(o[jj][2] * inv1, o[jj][3] * inv1);
  }
}

// ---------------------------------------------------------------------------
extern "C" void kernel_launch(void* const* d_in, const int* in_sizes, int n_in,
                              void* d_out, int out_size) {
  (void)in_sizes; (void)n_in; (void)out_size;
  const float* x  = (const float*)d_in[0];
  const float* Wk = (const float*)d_in[1];
  // d_in[2] is Wq — unused (reference uses Wk for q too).
  const float* Wv = (const float*)d_in[3];
  float* out = (float*)d_out;

  proj_kernel<<<dim3(128, 2), 256>>>(x, Wk, Wv);

  cudaFuncSetAttribute(flash_kernel,
                       cudaFuncAttributeMaxDynamicSharedMemorySize,
                       FA_SMEM_BYTES);
  flash_kernel<<<256, 256, FA_SMEM_BYTES>>>(out);
}